// round 12
// baseline (speedup 1.0000x reference)
#include <cuda_runtime.h>

#define N_NODES 50000
#define N_EDGES 800000
#define N_RELS  500
#define HID     128
#define NH      8
#define NB      64
#define SLOPE   0.2f
#define NW      ((N_NODES + 31) / 32)   // bitmask words
#define NPB     8                       // rows per block in tiled GEMV kernels
#define RELBLK  ((N_RELS + NPB - 1) / NPB)   // 63 rel blocks per layer
#define CBLKS   ((NW + 255) / 256)      // 7 compact blocks

// -------- static device scratch --------
__device__ float g_feat[(size_t)N_NODES * HID];
__device__ float g_h1[(size_t)N_NODES * HID];     // layer-1 numerator; h1 = numer/denomA
__device__ float g_el[N_NODES * NH];
__device__ float g_er[N_NODES * NH];
__device__ float g_denomA[N_NODES * NH];
__device__ float g_denomB[NB * NH];
__device__ int4  g_E1[N_EDGES];            // {src, dst, rel, 0}
__device__ int4  g_E2[N_EDGES];            // {src, dst, rel, batch}
__device__ int   g_listN0[N_NODES];
__device__ int   g_listN1[N_NODES];
__device__ unsigned g_bmS2[NW];
__device__ unsigned g_bmN1[NW];
__device__ unsigned g_bmN0[NW];
__device__ int   g_b_of_node[N_NODES];
__device__ int   g_cnt[4];                 // 0:|E2| 1:|E1| 2:|N0| 3:|N1|
__device__ int   g_done;
__device__ float g_rproj[2 * N_RELS * HID];
__device__ float g_ee[2 * N_RELS * NH];

// -------- helpers --------
__device__ __forceinline__ int warp_reserve(int c, int* counter, int lane) {
    int pre = c;
#pragma unroll
    for (int off = 1; off < 32; off <<= 1) {
        int v = __shfl_up_sync(0xffffffffu, pre, off);
        if (lane >= off) pre += v;
    }
    int total = __shfl_sync(0xffffffffu, pre, 31);
    int base = 0;
    if (lane == 31 && total) base = atomicAdd(counter, total);
    base = __shfl_sync(0xffffffffu, base, 31);
    return base + pre - c;
}
__device__ __forceinline__ int bit_test(const unsigned* bm, int n) {
    return (bm[n >> 5] >> (n & 31)) & 1;
}
__device__ __forceinline__ void ffma2(unsigned long long& d,
                                      unsigned long long a, unsigned long long b) {
    asm("fma.rn.f32x2 %0, %1, %2, %0;" : "+l"(d) : "l"(a), "l"(b));
}
__device__ __forceinline__ void unpack2(unsigned long long v, float& lo, float& hi) {
    asm("mov.b64 {%0, %1}, %2;" : "=f"(lo), "=f"(hi) : "l"(v));
}

// -------- kernels --------
// single-block init + seed
__global__ void k_init(float* __restrict__ dout, const int* __restrict__ offs) {
    int tid = threadIdx.x;   // 256
    for (int i = tid; i < NW; i += 256) { g_bmS2[i] = 0u; g_bmN1[i] = 0u; g_bmN0[i] = 0u; }
    for (int i = tid; i < NB * HID; i += 256) dout[i] = 0.0f;
    for (int i = tid; i < NB * NH; i += 256) g_denomB[i] = 0.0f;
    if (tid < 4) g_cnt[tid] = 0;
    if (tid == 4) g_done = 0;
    __syncthreads();
    if (tid < NB) {
        int n = offs[tid];
        atomicOr(&g_bmS2[n >> 5], 1u << (n & 31));
        atomicOr(&g_bmN1[n >> 5], 1u << (n & 31));
        g_b_of_node[n] = tid;
    }
}

// layer-2 edge filter: dst in S2. Two int4 chunks (8 edges) per thread.
__global__ void k_filter2(const int4* __restrict__ src4, const int4* __restrict__ dst4,
                          const int* __restrict__ rel_ids) {
    const int half = N_EDGES / 8;
    int base = blockIdx.x * blockDim.x + threadIdx.x;
    int lane = threadIdx.x & 31;
    unsigned m0 = 0, m1 = 0;
    int4 d0, d1;
    if (base < half) {
        d0 = __ldg(&dst4[base]);
        d1 = __ldg(&dst4[base + half]);
        unsigned w0 = g_bmS2[d0.x >> 5], w1 = g_bmS2[d0.y >> 5];
        unsigned w2 = g_bmS2[d0.z >> 5], w3 = g_bmS2[d0.w >> 5];
        unsigned w4 = g_bmS2[d1.x >> 5], w5 = g_bmS2[d1.y >> 5];
        unsigned w6 = g_bmS2[d1.z >> 5], w7 = g_bmS2[d1.w >> 5];
        m0 = ((w0 >> (d0.x & 31)) & 1u) | (((w1 >> (d0.y & 31)) & 1u) << 1)
           | (((w2 >> (d0.z & 31)) & 1u) << 2) | (((w3 >> (d0.w & 31)) & 1u) << 3);
        m1 = ((w4 >> (d1.x & 31)) & 1u) | (((w5 >> (d1.y & 31)) & 1u) << 1)
           | (((w6 >> (d1.z & 31)) & 1u) << 2) | (((w7 >> (d1.w & 31)) & 1u) << 3);
    }
    int c = __popc(m0) + __popc(m1);
    int pos = warp_reserve(c, &g_cnt[0], lane);
    if (m0) {
        int i0 = base;
        int4 s = __ldg(&src4[i0]);
        if (m0 & 1u) { g_E2[pos++] = make_int4(s.x, d0.x, __ldg(&rel_ids[4*i0+0]), g_b_of_node[d0.x]); atomicOr(&g_bmN1[s.x >> 5], 1u << (s.x & 31)); }
        if (m0 & 2u) { g_E2[pos++] = make_int4(s.y, d0.y, __ldg(&rel_ids[4*i0+1]), g_b_of_node[d0.y]); atomicOr(&g_bmN1[s.y >> 5], 1u << (s.y & 31)); }
        if (m0 & 4u) { g_E2[pos++] = make_int4(s.z, d0.z, __ldg(&rel_ids[4*i0+2]), g_b_of_node[d0.z]); atomicOr(&g_bmN1[s.z >> 5], 1u << (s.z & 31)); }
        if (m0 & 8u) { g_E2[pos++] = make_int4(s.w, d0.w, __ldg(&rel_ids[4*i0+3]), g_b_of_node[d0.w]); atomicOr(&g_bmN1[s.w >> 5], 1u << (s.w & 31)); }
    }
    if (m1) {
        int i1 = base + half;
        int4 s = __ldg(&src4[i1]);
        if (m1 & 1u) { g_E2[pos++] = make_int4(s.x, d1.x, __ldg(&rel_ids[4*i1+0]), g_b_of_node[d1.x]); atomicOr(&g_bmN1[s.x >> 5], 1u << (s.x & 31)); }
        if (m1 & 2u) { g_E2[pos++] = make_int4(s.y, d1.y, __ldg(&rel_ids[4*i1+1]), g_b_of_node[d1.y]); atomicOr(&g_bmN1[s.y >> 5], 1u << (s.y & 31)); }
        if (m1 & 4u) { g_E2[pos++] = make_int4(s.z, d1.z, __ldg(&rel_ids[4*i1+2]), g_b_of_node[d1.z]); atomicOr(&g_bmN1[s.z >> 5], 1u << (s.z & 31)); }
        if (m1 & 8u) { g_E2[pos++] = make_int4(s.w, d1.w, __ldg(&rel_ids[4*i1+3]), g_b_of_node[d1.w]); atomicOr(&g_bmN1[s.w >> 5], 1u << (s.w & 31)); }
    }
}

// layer-1 edge filter: dst in N1
__global__ void k_filter1(const int4* __restrict__ src4, const int4* __restrict__ dst4,
                          const int* __restrict__ rel_ids) {
    const int half = N_EDGES / 8;
    int base = blockIdx.x * blockDim.x + threadIdx.x;
    int lane = threadIdx.x & 31;
    unsigned m0 = 0, m1 = 0;
    int4 d0, d1;
    if (base < half) {
        d0 = __ldg(&dst4[base]);
        d1 = __ldg(&dst4[base + half]);
        unsigned w0 = g_bmN1[d0.x >> 5], w1 = g_bmN1[d0.y >> 5];
        unsigned w2 = g_bmN1[d0.z >> 5], w3 = g_bmN1[d0.w >> 5];
        unsigned w4 = g_bmN1[d1.x >> 5], w5 = g_bmN1[d1.y >> 5];
        unsigned w6 = g_bmN1[d1.z >> 5], w7 = g_bmN1[d1.w >> 5];
        m0 = ((w0 >> (d0.x & 31)) & 1u) | (((w1 >> (d0.y & 31)) & 1u) << 1)
           | (((w2 >> (d0.z & 31)) & 1u) << 2) | (((w3 >> (d0.w & 31)) & 1u) << 3);
        m1 = ((w4 >> (d1.x & 31)) & 1u) | (((w5 >> (d1.y & 31)) & 1u) << 1)
           | (((w6 >> (d1.z & 31)) & 1u) << 2) | (((w7 >> (d1.w & 31)) & 1u) << 3);
    }
    int c = __popc(m0) + __popc(m1);
    int pos = warp_reserve(c, &g_cnt[1], lane);
    if (m0) {
        int i0 = base;
        int4 s = __ldg(&src4[i0]);
        if (m0 & 1u) { g_E1[pos++] = make_int4(s.x, d0.x, __ldg(&rel_ids[4*i0+0]), 0); atomicOr(&g_bmN0[s.x >> 5], 1u << (s.x & 31)); }
        if (m0 & 2u) { g_E1[pos++] = make_int4(s.y, d0.y, __ldg(&rel_ids[4*i0+1]), 0); atomicOr(&g_bmN0[s.y >> 5], 1u << (s.y & 31)); }
        if (m0 & 4u) { g_E1[pos++] = make_int4(s.z, d0.z, __ldg(&rel_ids[4*i0+2]), 0); atomicOr(&g_bmN0[s.z >> 5], 1u << (s.z & 31)); }
        if (m0 & 8u) { g_E1[pos++] = make_int4(s.w, d0.w, __ldg(&rel_ids[4*i0+3]), 0); atomicOr(&g_bmN0[s.w >> 5], 1u << (s.w & 31)); }
    }
    if (m1) {
        int i1 = base + half;
        int4 s = __ldg(&src4[i1]);
        if (m1 & 1u) { g_E1[pos++] = make_int4(s.x, d1.x, __ldg(&rel_ids[4*i1+0]), 0); atomicOr(&g_bmN0[s.x >> 5], 1u << (s.x & 31)); }
        if (m1 & 2u) { g_E1[pos++] = make_int4(s.y, d1.y, __ldg(&rel_ids[4*i1+1]), 0); atomicOr(&g_bmN0[s.y >> 5], 1u << (s.y & 31)); }
        if (m1 & 4u) { g_E1[pos++] = make_int4(s.z, d1.z, __ldg(&rel_ids[4*i1+2]), 0); atomicOr(&g_bmN0[s.z >> 5], 1u << (s.z & 31)); }
        if (m1 & 8u) { g_E1[pos++] = make_int4(s.w, d1.w, __ldg(&rel_ids[4*i1+3]), 0); atomicOr(&g_bmN0[s.w >> 5], 1u << (s.w & 31)); }
    }
}

// blocks [0, CBLKS): word-parallel node-list compaction.
// blocks [CBLKS, CBLKS + 2*RELBLK): relation projection + attention scores
// (riding in the shadow of the compact blocks' latency). 256 threads.
__global__ void k_compact_rel(const float* __restrict__ rel_table,
                              const float* __restrict__ W_rel,
                              const float* __restrict__ attn_e) {
    int tid = threadIdx.x;
    if (blockIdx.x < CBLKS) {
        int idx = blockIdx.x * 256 + tid;
        int lane = tid & 31;
        unsigned w1 = 0, w0 = 0;
        if (idx < NW) {
            w1 = g_bmN1[idx];
            w0 = g_bmN0[idx] | w1;
        }
        int c0 = __popc(w0), c1 = __popc(w1);
        int p0 = warp_reserve(c0, &g_cnt[2], lane);
        int p1 = warp_reserve(c1, &g_cnt[3], lane);
        int nb = idx << 5;
        while (w0) { int b = __ffs(w0) - 1; w0 &= w0 - 1; g_listN0[p0++] = nb + b; }
        while (w1) { int b = __ffs(w1) - 1; w1 &= w1 - 1; g_listN1[p1++] = nb + b; }
        return;
    }
    // ---- relation GEMV: 8 rels/block, 256 threads (4 groups x 2 rels) ----
    __shared__ float2 s2[NPB][HID + 2];
    int rb = blockIdx.x - CBLKS;           // 0 .. 2*RELBLK-1
    int l = rb / RELBLK;
    int base = (rb % RELBLK) * NPB;
    int t = tid & 63;
    int g = tid >> 6;                      // 0..3
    const float* W = W_rel + (size_t)l * HID * HID;
    float ae0 = attn_e[l * HID + 2 * t], ae1 = attn_e[l * HID + 2 * t + 1];

    for (int idx = tid; idx < NPB * 32; idx += 256) {
        int n = idx >> 5, q = idx & 31;
        float4 v = make_float4(0.f, 0.f, 0.f, 0.f);
        if (base + n < N_RELS)
            v = *(const float4*)(rel_table + (size_t)(base + n) * HID + 4 * q);
        s2[n][4 * q + 0] = make_float2(v.x, v.x);
        s2[n][4 * q + 1] = make_float2(v.y, v.y);
        s2[n][4 * q + 2] = make_float2(v.z, v.z);
        s2[n][4 * q + 3] = make_float2(v.w, v.w);
    }
    __syncthreads();

    unsigned long long acc0 = 0, acc1 = 0;
    int n0 = g * 2;
#pragma unroll 4
    for (int k = 0; k < HID; k++) {
        unsigned long long w = *(const unsigned long long*)(W + (size_t)k * HID + 2 * t);
        ffma2(acc0, *(const unsigned long long*)&s2[n0 + 0][k], w);
        ffma2(acc1, *(const unsigned long long*)&s2[n0 + 1][k], w);
    }

    unsigned long long accs[2] = {acc0, acc1};
#pragma unroll
    for (int n = 0; n < 2; n++) {
        float f0, f1;
        unpack2(accs[n], f0, f1);
        float pe = f0 * ae0 + f1 * ae1;
        pe += __shfl_xor_sync(0xffffffffu, pe, 4);
        pe += __shfl_xor_sync(0xffffffffu, pe, 2);
        pe += __shfl_xor_sync(0xffffffffu, pe, 1);
        int r = base + n0 + n;
        if (r < N_RELS) {
            int b = l * N_RELS + r;
            *(float2*)(g_rproj + (size_t)b * HID + 2 * t) = make_float2(f0, f1);
            if ((t & 7) == 0) g_ee[b * NH + (t >> 3)] = pe;
        }
    }
}

// node projection + el/er. 8 nodes/block, 128 threads, f32x2 packed FMA.
// (R7-proven layout: t = tid&63 owns col pair, g = tid>>6 owns 4 nodes.)
// layer==0: also zeroes g_h1/denomA rows for nodes in N1.
// layer==1: input rows are g_h1 numerators, divided by denomA at load.
__global__ void k_node(int layer,
                       const float* __restrict__ ent_table,
                       const int*   __restrict__ ent_ids,
                       const float* __restrict__ W_ent,
                       const float* __restrict__ attn_l,
                       const float* __restrict__ attn_r) {
    __shared__ float2 s2[NPB][HID + 2];
    int tid = threadIdx.x;
    int t = tid & 63;
    int g = tid >> 6;
    int cnt = (layer == 0) ? g_cnt[2] : g_cnt[3];
    const int* list = (layer == 0) ? g_listN0 : g_listN1;
    const float* W = W_ent + (size_t)layer * HID * HID;
    float al0 = attn_l[layer * HID + 2 * t], al1 = attn_l[layer * HID + 2 * t + 1];
    float ar0 = attn_r[layer * HID + 2 * t], ar1 = attn_r[layer * HID + 2 * t + 1];

    for (int base = blockIdx.x * NPB; base < cnt; base += gridDim.x * NPB) {
        __syncthreads();
        for (int idx = tid; idx < NPB * 32; idx += 128) {
            int n = idx >> 5, q = idx & 31;
            float4 v = make_float4(0.f, 0.f, 0.f, 0.f);
            int gi = base + n;
            if (gi < cnt) {
                int node = list[gi];
                if (layer == 0) {
                    v = *(const float4*)(ent_table + (size_t)__ldg(&ent_ids[node]) * HID + 4 * q);
                } else {
                    v = *(const float4*)(g_h1 + (size_t)node * HID + 4 * q);
                    float den = g_denomA[node * NH + (q >> 2)];
                    float inv = (den != 0.0f) ? __frcp_rn(den) : 0.0f;
                    v.x *= inv; v.y *= inv; v.z *= inv; v.w *= inv;
                }
            }
            s2[n][4 * q + 0] = make_float2(v.x, v.x);
            s2[n][4 * q + 1] = make_float2(v.y, v.y);
            s2[n][4 * q + 2] = make_float2(v.z, v.z);
            s2[n][4 * q + 3] = make_float2(v.w, v.w);
        }
        __syncthreads();

        unsigned long long acc0 = 0, acc1 = 0, acc2 = 0, acc3 = 0;
        int n0 = g * 4;
#pragma unroll 4
        for (int k = 0; k < HID; k += 4) {
            unsigned long long w0 = *(const unsigned long long*)(W + (size_t)(k + 0) * HID + 2 * t);
            unsigned long long w1 = *(const unsigned long long*)(W + (size_t)(k + 1) * HID + 2 * t);
            unsigned long long w2 = *(const unsigned long long*)(W + (size_t)(k + 2) * HID + 2 * t);
            unsigned long long w3 = *(const unsigned long long*)(W + (size_t)(k + 3) * HID + 2 * t);
            ffma2(acc0, *(const unsigned long long*)&s2[n0 + 0][k + 0], w0);
            ffma2(acc1, *(const unsigned long long*)&s2[n0 + 1][k + 0], w0);
            ffma2(acc2, *(const unsigned long long*)&s2[n0 + 2][k + 0], w0);
            ffma2(acc3, *(const unsigned long long*)&s2[n0 + 3][k + 0], w0);
            ffma2(acc0, *(const unsigned long long*)&s2[n0 + 0][k + 1], w1);
            ffma2(acc1, *(const unsigned long long*)&s2[n0 + 1][k + 1], w1);
            ffma2(acc2, *(const unsigned long long*)&s2[n0 + 2][k + 1], w1);
            ffma2(acc3, *(const unsigned long long*)&s2[n0 + 3][k + 1], w1);
            ffma2(acc0, *(const unsigned long long*)&s2[n0 + 0][k + 2], w2);
            ffma2(acc1, *(const unsigned long long*)&s2[n0 + 1][k + 2], w2);
            ffma2(acc2, *(const unsigned long long*)&s2[n0 + 2][k + 2], w2);
            ffma2(acc3, *(const unsigned long long*)&s2[n0 + 3][k + 2], w2);
            ffma2(acc0, *(const unsigned long long*)&s2[n0 + 0][k + 3], w3);
            ffma2(acc1, *(const unsigned long long*)&s2[n0 + 1][k + 3], w3);
            ffma2(acc2, *(const unsigned long long*)&s2[n0 + 2][k + 3], w3);
            ffma2(acc3, *(const unsigned long long*)&s2[n0 + 3][k + 3], w3);
        }

        unsigned long long accs[4] = {acc0, acc1, acc2, acc3};
#pragma unroll
        for (int n = 0; n < 4; n++) {
            float f0, f1;
            unpack2(accs[n], f0, f1);
            float pl = f0 * al0 + f1 * al1;
            float pr = f0 * ar0 + f1 * ar1;
            pl += __shfl_xor_sync(0xffffffffu, pl, 4);
            pl += __shfl_xor_sync(0xffffffffu, pl, 2);
            pl += __shfl_xor_sync(0xffffffffu, pl, 1);
            pr += __shfl_xor_sync(0xffffffffu, pr, 4);
            pr += __shfl_xor_sync(0xffffffffu, pr, 2);
            pr += __shfl_xor_sync(0xffffffffu, pr, 1);
            int gi = base + n0 + n;
            if (gi < cnt) {
                int node = list[gi];
                *(float2*)(g_feat + (size_t)node * HID + 2 * t) = make_float2(f0, f1);
                if ((t & 7) == 0) {
                    g_el[node * NH + (t >> 3)] = pl;
                    g_er[node * NH + (t >> 3)] = pr;
                }
                if (layer == 0 && bit_test(g_bmN1, node)) {
                    *(float2*)(g_h1 + (size_t)node * HID + 2 * t) = make_float2(0.f, 0.f);
                    if (t < NH) g_denomA[node * NH + t] = 0.0f;
                }
            }
        }
    }
}

// fused edge pass: ex = exp(leakyrelu(el+er+ee)); accumulate
// denominator Σex and NUMERATOR Σ ex*(feat[src]+rproj[rel]).
// layer==1 (64-block grid): last finishing block normalizes the output.
__global__ void k_edge(int layer, float* __restrict__ dout) {
    int cnt = (layer == 0) ? g_cnt[1] : g_cnt[0];
    const int4* El = (layer == 0) ? g_E1 : g_E2;
    int t = blockIdx.x * blockDim.x + threadIdx.x;
    int j = t & 31;
    int h = j >> 2;
    int e0 = t >> 5;
    int stride = (gridDim.x * blockDim.x) >> 5;
    for (int e = e0; e < cnt; e += stride) {
        int4 p = El[e];
        float v = g_el[p.x * NH + h] + g_er[p.y * NH + h]
                + g_ee[(layer * N_RELS + p.z) * NH + h];
        v = (v > 0.0f) ? v : SLOPE * v;
        float ex = expf(v);
        if ((j & 3) == 0) {
            if (layer == 0) atomicAdd(&g_denomA[p.y * NH + h], ex);
            else            atomicAdd(&g_denomB[p.w * NH + h], ex);
        }
        float4 f  = *(const float4*)(g_feat  + (size_t)p.x * HID + 4 * j);
        float4 rp = *(const float4*)(g_rproj + (size_t)(layer * N_RELS + p.z) * HID + 4 * j);
        float* ob = (layer == 0) ? (g_h1 + (size_t)p.y * HID)
                                 : (dout + (size_t)p.w * HID);
        atomicAdd(ob + 4 * j + 0, (f.x + rp.x) * ex);
        atomicAdd(ob + 4 * j + 1, (f.y + rp.y) * ex);
        atomicAdd(ob + 4 * j + 2, (f.z + rp.z) * ex);
        atomicAdd(ob + 4 * j + 3, (f.w + rp.w) * ex);
    }
    if (layer == 1) {
        // small grid (64 blocks) -> fence + done-counter is cheap here
        __shared__ int s_last;
        __threadfence();
        __syncthreads();
        if (threadIdx.x == 0)
            s_last = (atomicAdd(&g_done, 1) == (int)gridDim.x - 1);
        __syncthreads();
        if (!s_last) return;
        __threadfence();
        for (int i = threadIdx.x; i < NB * HID; i += blockDim.x) {
            int b = i >> 7, col = i & 127;
            float den = g_denomB[b * NH + (col >> 4)];
            float inv = (den != 0.0f) ? __frcp_rn(den) : 0.0f;
            dout[i] *= inv;
        }
    }
}

// -------- launch --------
extern "C" void kernel_launch(void* const* d_in, const int* in_sizes, int n_in,
                              void* d_out, int out_size) {
    const float* ent_table = (const float*)d_in[0];
    const float* rel_table = (const float*)d_in[1];
    const float* W_ent     = (const float*)d_in[2];
    const float* W_rel     = (const float*)d_in[3];
    const float* attn_l    = (const float*)d_in[4];
    const float* attn_r    = (const float*)d_in[5];
    const float* attn_e    = (const float*)d_in[6];
    const int*   ent_ids   = (const int*)d_in[7];
    const int*   rel_ids   = (const int*)d_in[8];
    const int*   src       = (const int*)d_in[9];
    const int*   dst       = (const int*)d_in[10];
    const int*   goffs     = (const int*)d_in[11];
    float*       out       = (float*)d_out;

    k_init<<<1, 256>>>(out, goffs);
    k_filter2<<<(N_EDGES / 8 + 255) / 256, 256>>>((const int4*)src, (const int4*)dst, rel_ids);
    k_filter1<<<(N_EDGES / 8 + 255) / 256, 256>>>((const int4*)src, (const int4*)dst, rel_ids);
    k_compact_rel<<<CBLKS + 2 * RELBLK, 256>>>(rel_table, W_rel, attn_e);

    // layer 0 (full frontier N0)
    k_node<<<2048, 128>>>(0, ent_table, ent_ids, W_ent, attn_l, attn_r);
    k_edge<<<512, 256>>>(0, out);

    // layer 1 (frontier N1, output rows only)
    k_node<<<256, 128>>>(1, ent_table, ent_ids, W_ent, attn_l, attn_r);
    k_edge<<<64, 256>>>(1, out);
}

// round 13
// speedup vs baseline: 1.2033x; 1.2033x over previous
#include <cuda_runtime.h>

#define N_NODES 50000
#define N_EDGES 800000
#define N_RELS  500
#define HID     128
#define NH      8
#define NB      64
#define SLOPE   0.2f
#define NW      ((N_NODES + 31) / 32)   // bitmask words
#define NPB     8                       // rows per block in k_node
#define RPB     16                      // rels per block in filter2's rel blocks (256 thr)
#define RELBLK  ((N_RELS + RPB - 1) / RPB)   // 32 rel blocks per layer
#define F2BLKS  ((N_EDGES / 8 + 255) / 256)  // 391 filter2 blocks

// -------- static device scratch --------
__device__ float g_feat[(size_t)N_NODES * HID];
__device__ float g_h1[(size_t)N_NODES * HID];     // layer-1 numerator; h1 = numer/denomA
__device__ float g_el[N_NODES * NH];
__device__ float g_er[N_NODES * NH];
__device__ float g_denomA[N_NODES * NH];
__device__ float g_denomB[NB * NH];
__device__ int4  g_E1[N_EDGES];            // {src, dst, rel, 0}
__device__ int4  g_E2[N_EDGES];            // {src, dst, rel, batch}
__device__ int   g_listN0[N_NODES];
__device__ int   g_listN1[N_NODES];
__device__ unsigned g_bmS2[NW];
__device__ unsigned g_bmN1[NW];
__device__ unsigned g_bmN0[NW];
__device__ int   g_b_of_node[N_NODES];
__device__ int   g_cnt[4];                 // 0:|E2| 1:|E1| 2:|N0| 3:|N1|
__device__ float g_rproj[2 * N_RELS * HID];
__device__ float g_ee[2 * N_RELS * NH];

// -------- helpers --------
__device__ __forceinline__ int warp_reserve(int c, int* counter, int lane) {
    int pre = c;
#pragma unroll
    for (int off = 1; off < 32; off <<= 1) {
        int v = __shfl_up_sync(0xffffffffu, pre, off);
        if (lane >= off) pre += v;
    }
    int total = __shfl_sync(0xffffffffu, pre, 31);
    int base = 0;
    if (lane == 31 && total) base = atomicAdd(counter, total);
    base = __shfl_sync(0xffffffffu, base, 31);
    return base + pre - c;
}
__device__ __forceinline__ int bit_test(const unsigned* bm, int n) {
    return (bm[n >> 5] >> (n & 31)) & 1;
}
__device__ __forceinline__ void ffma2(unsigned long long& d,
                                      unsigned long long a, unsigned long long b) {
    asm("fma.rn.f32x2 %0, %1, %2, %0;" : "+l"(d) : "l"(a), "l"(b));
}
__device__ __forceinline__ void unpack2(unsigned long long v, float& lo, float& hi) {
    asm("mov.b64 {%0, %1}, %2;" : "=f"(lo), "=f"(hi) : "l"(v));
}

// -------- kernels --------
// single-block init + seed
__global__ void k_init(float* __restrict__ dout, const int* __restrict__ offs) {
    int tid = threadIdx.x;   // 256
    for (int i = tid; i < NW; i += 256) { g_bmS2[i] = 0u; g_bmN1[i] = 0u; g_bmN0[i] = 0u; }
    for (int i = tid; i < NB * HID; i += 256) dout[i] = 0.0f;
    for (int i = tid; i < NB * NH; i += 256) g_denomB[i] = 0.0f;
    if (tid < 4) g_cnt[tid] = 0;
    __syncthreads();
    if (tid < NB) {
        int n = offs[tid];
        atomicOr(&g_bmS2[n >> 5], 1u << (n & 31));
        atomicOr(&g_bmN1[n >> 5], 1u << (n & 31));
        g_b_of_node[n] = tid;
    }
}

// blocks [0, F2BLKS): layer-2 edge filter (dst in S2), 8 edges/thread (R7 form).
// blocks [F2BLKS, F2BLKS + 2*RELBLK): relation projection + attention scores,
// riding in the filter's shadow. R7-proven 4-accumulator inner loop, 16 rels/block.
__global__ void k_filter2_rel(const int4* __restrict__ src4, const int4* __restrict__ dst4,
                              const int* __restrict__ rel_ids,
                              const float* __restrict__ rel_table,
                              const float* __restrict__ W_rel,
                              const float* __restrict__ attn_e) {
    __shared__ float2 s2[RPB][HID + 2];
    int tid = threadIdx.x;

    if (blockIdx.x < F2BLKS) {
        // ---------- filter2 path (byte-identical logic to R7) ----------
        const int half = N_EDGES / 8;
        int base = blockIdx.x * 256 + tid;
        int lane = tid & 31;
        unsigned m0 = 0, m1 = 0;
        int4 d0, d1;
        if (base < half) {
            d0 = __ldg(&dst4[base]);
            d1 = __ldg(&dst4[base + half]);
            unsigned w0 = g_bmS2[d0.x >> 5], w1 = g_bmS2[d0.y >> 5];
            unsigned w2 = g_bmS2[d0.z >> 5], w3 = g_bmS2[d0.w >> 5];
            unsigned w4 = g_bmS2[d1.x >> 5], w5 = g_bmS2[d1.y >> 5];
            unsigned w6 = g_bmS2[d1.z >> 5], w7 = g_bmS2[d1.w >> 5];
            m0 = ((w0 >> (d0.x & 31)) & 1u) | (((w1 >> (d0.y & 31)) & 1u) << 1)
               | (((w2 >> (d0.z & 31)) & 1u) << 2) | (((w3 >> (d0.w & 31)) & 1u) << 3);
            m1 = ((w4 >> (d1.x & 31)) & 1u) | (((w5 >> (d1.y & 31)) & 1u) << 1)
               | (((w6 >> (d1.z & 31)) & 1u) << 2) | (((w7 >> (d1.w & 31)) & 1u) << 3);
        }
        int c = __popc(m0) + __popc(m1);
        int pos = warp_reserve(c, &g_cnt[0], lane);
        if (m0) {
            int i0 = base;
            int4 s = __ldg(&src4[i0]);
            if (m0 & 1u) { g_E2[pos++] = make_int4(s.x, d0.x, __ldg(&rel_ids[4*i0+0]), g_b_of_node[d0.x]); atomicOr(&g_bmN1[s.x >> 5], 1u << (s.x & 31)); }
            if (m0 & 2u) { g_E2[pos++] = make_int4(s.y, d0.y, __ldg(&rel_ids[4*i0+1]), g_b_of_node[d0.y]); atomicOr(&g_bmN1[s.y >> 5], 1u << (s.y & 31)); }
            if (m0 & 4u) { g_E2[pos++] = make_int4(s.z, d0.z, __ldg(&rel_ids[4*i0+2]), g_b_of_node[d0.z]); atomicOr(&g_bmN1[s.z >> 5], 1u << (s.z & 31)); }
            if (m0 & 8u) { g_E2[pos++] = make_int4(s.w, d0.w, __ldg(&rel_ids[4*i0+3]), g_b_of_node[d0.w]); atomicOr(&g_bmN1[s.w >> 5], 1u << (s.w & 31)); }
        }
        if (m1) {
            int i1 = base + half;
            int4 s = __ldg(&src4[i1]);
            if (m1 & 1u) { g_E2[pos++] = make_int4(s.x, d1.x, __ldg(&rel_ids[4*i1+0]), g_b_of_node[d1.x]); atomicOr(&g_bmN1[s.x >> 5], 1u << (s.x & 31)); }
            if (m1 & 2u) { g_E2[pos++] = make_int4(s.y, d1.y, __ldg(&rel_ids[4*i1+1]), g_b_of_node[d1.y]); atomicOr(&g_bmN1[s.y >> 5], 1u << (s.y & 31)); }
            if (m1 & 4u) { g_E2[pos++] = make_int4(s.z, d1.z, __ldg(&rel_ids[4*i1+2]), g_b_of_node[d1.z]); atomicOr(&g_bmN1[s.z >> 5], 1u << (s.z & 31)); }
            if (m1 & 8u) { g_E2[pos++] = make_int4(s.w, d1.w, __ldg(&rel_ids[4*i1+3]), g_b_of_node[d1.w]); atomicOr(&g_bmN1[s.w >> 5], 1u << (s.w & 31)); }
        }
        return;
    }

    // ---------- relation GEMV path (R7 inner loop, 4 accs, 16 rels/block) ----------
    int rb = blockIdx.x - F2BLKS;          // 0 .. 2*RELBLK-1
    int l = rb / RELBLK;
    int base = (rb % RELBLK) * RPB;
    int t = tid & 63;
    int g = tid >> 6;                      // 0..3
    const float* W = W_rel + (size_t)l * HID * HID;
    float ae0 = attn_e[l * HID + 2 * t], ae1 = attn_e[l * HID + 2 * t + 1];

    for (int idx = tid; idx < RPB * 32; idx += 256) {
        int n = idx >> 5, q = idx & 31;
        float4 v = make_float4(0.f, 0.f, 0.f, 0.f);
        if (base + n < N_RELS)
            v = *(const float4*)(rel_table + (size_t)(base + n) * HID + 4 * q);
        s2[n][4 * q + 0] = make_float2(v.x, v.x);
        s2[n][4 * q + 1] = make_float2(v.y, v.y);
        s2[n][4 * q + 2] = make_float2(v.z, v.z);
        s2[n][4 * q + 3] = make_float2(v.w, v.w);
    }
    __syncthreads();

    unsigned long long acc0 = 0, acc1 = 0, acc2 = 0, acc3 = 0;
    int n0 = g * 4;
#pragma unroll 4
    for (int k = 0; k < HID; k += 4) {
        unsigned long long w0 = *(const unsigned long long*)(W + (size_t)(k + 0) * HID + 2 * t);
        unsigned long long w1 = *(const unsigned long long*)(W + (size_t)(k + 1) * HID + 2 * t);
        unsigned long long w2 = *(const unsigned long long*)(W + (size_t)(k + 2) * HID + 2 * t);
        unsigned long long w3 = *(const unsigned long long*)(W + (size_t)(k + 3) * HID + 2 * t);
        ffma2(acc0, *(const unsigned long long*)&s2[n0 + 0][k + 0], w0);
        ffma2(acc1, *(const unsigned long long*)&s2[n0 + 1][k + 0], w0);
        ffma2(acc2, *(const unsigned long long*)&s2[n0 + 2][k + 0], w0);
        ffma2(acc3, *(const unsigned long long*)&s2[n0 + 3][k + 0], w0);
        ffma2(acc0, *(const unsigned long long*)&s2[n0 + 0][k + 1], w1);
        ffma2(acc1, *(const unsigned long long*)&s2[n0 + 1][k + 1], w1);
        ffma2(acc2, *(const unsigned long long*)&s2[n0 + 2][k + 1], w1);
        ffma2(acc3, *(const unsigned long long*)&s2[n0 + 3][k + 1], w1);
        ffma2(acc0, *(const unsigned long long*)&s2[n0 + 0][k + 2], w2);
        ffma2(acc1, *(const unsigned long long*)&s2[n0 + 1][k + 2], w2);
        ffma2(acc2, *(const unsigned long long*)&s2[n0 + 2][k + 2], w2);
        ffma2(acc3, *(const unsigned long long*)&s2[n0 + 3][k + 2], w2);
        ffma2(acc0, *(const unsigned long long*)&s2[n0 + 0][k + 3], w3);
        ffma2(acc1, *(const unsigned long long*)&s2[n0 + 1][k + 3], w3);
        ffma2(acc2, *(const unsigned long long*)&s2[n0 + 2][k + 3], w3);
        ffma2(acc3, *(const unsigned long long*)&s2[n0 + 3][k + 3], w3);
    }

    unsigned long long accs[4] = {acc0, acc1, acc2, acc3};
#pragma unroll
    for (int n = 0; n < 4; n++) {
        float f0, f1;
        unpack2(accs[n], f0, f1);
        float pe = f0 * ae0 + f1 * ae1;
        pe += __shfl_xor_sync(0xffffffffu, pe, 4);
        pe += __shfl_xor_sync(0xffffffffu, pe, 2);
        pe += __shfl_xor_sync(0xffffffffu, pe, 1);
        int r = base + n0 + n;
        if (r < N_RELS) {
            int b = l * N_RELS + r;
            *(float2*)(g_rproj + (size_t)b * HID + 2 * t) = make_float2(f0, f1);
            if ((t & 7) == 0) g_ee[b * NH + (t >> 3)] = pe;
        }
    }
}

// layer-1 edge filter: dst in N1 (R7 form)
__global__ void k_filter1(const int4* __restrict__ src4, const int4* __restrict__ dst4,
                          const int* __restrict__ rel_ids) {
    const int half = N_EDGES / 8;
    int base = blockIdx.x * blockDim.x + threadIdx.x;
    int lane = threadIdx.x & 31;
    unsigned m0 = 0, m1 = 0;
    int4 d0, d1;
    if (base < half) {
        d0 = __ldg(&dst4[base]);
        d1 = __ldg(&dst4[base + half]);
        unsigned w0 = g_bmN1[d0.x >> 5], w1 = g_bmN1[d0.y >> 5];
        unsigned w2 = g_bmN1[d0.z >> 5], w3 = g_bmN1[d0.w >> 5];
        unsigned w4 = g_bmN1[d1.x >> 5], w5 = g_bmN1[d1.y >> 5];
        unsigned w6 = g_bmN1[d1.z >> 5], w7 = g_bmN1[d1.w >> 5];
        m0 = ((w0 >> (d0.x & 31)) & 1u) | (((w1 >> (d0.y & 31)) & 1u) << 1)
           | (((w2 >> (d0.z & 31)) & 1u) << 2) | (((w3 >> (d0.w & 31)) & 1u) << 3);
        m1 = ((w4 >> (d1.x & 31)) & 1u) | (((w5 >> (d1.y & 31)) & 1u) << 1)
           | (((w6 >> (d1.z & 31)) & 1u) << 2) | (((w7 >> (d1.w & 31)) & 1u) << 3);
    }
    int c = __popc(m0) + __popc(m1);
    int pos = warp_reserve(c, &g_cnt[1], lane);
    if (m0) {
        int i0 = base;
        int4 s = __ldg(&src4[i0]);
        if (m0 & 1u) { g_E1[pos++] = make_int4(s.x, d0.x, __ldg(&rel_ids[4*i0+0]), 0); atomicOr(&g_bmN0[s.x >> 5], 1u << (s.x & 31)); }
        if (m0 & 2u) { g_E1[pos++] = make_int4(s.y, d0.y, __ldg(&rel_ids[4*i0+1]), 0); atomicOr(&g_bmN0[s.y >> 5], 1u << (s.y & 31)); }
        if (m0 & 4u) { g_E1[pos++] = make_int4(s.z, d0.z, __ldg(&rel_ids[4*i0+2]), 0); atomicOr(&g_bmN0[s.z >> 5], 1u << (s.z & 31)); }
        if (m0 & 8u) { g_E1[pos++] = make_int4(s.w, d0.w, __ldg(&rel_ids[4*i0+3]), 0); atomicOr(&g_bmN0[s.w >> 5], 1u << (s.w & 31)); }
    }
    if (m1) {
        int i1 = base + half;
        int4 s = __ldg(&src4[i1]);
        if (m1 & 1u) { g_E1[pos++] = make_int4(s.x, d1.x, __ldg(&rel_ids[4*i1+0]), 0); atomicOr(&g_bmN0[s.x >> 5], 1u << (s.x & 31)); }
        if (m1 & 2u) { g_E1[pos++] = make_int4(s.y, d1.y, __ldg(&rel_ids[4*i1+1]), 0); atomicOr(&g_bmN0[s.y >> 5], 1u << (s.y & 31)); }
        if (m1 & 4u) { g_E1[pos++] = make_int4(s.z, d1.z, __ldg(&rel_ids[4*i1+2]), 0); atomicOr(&g_bmN0[s.z >> 5], 1u << (s.z & 31)); }
        if (m1 & 8u) { g_E1[pos++] = make_int4(s.w, d1.w, __ldg(&rel_ids[4*i1+3]), 0); atomicOr(&g_bmN0[s.w >> 5], 1u << (s.w & 31)); }
    }
}

// word-parallel compaction: lists only (R7 form)
__global__ void k_compact() {
    int idx = blockIdx.x * blockDim.x + threadIdx.x;
    int lane = threadIdx.x & 31;
    unsigned w1 = 0, w0 = 0;
    if (idx < NW) {
        w1 = g_bmN1[idx];
        w0 = g_bmN0[idx] | w1;
    }
    int c0 = __popc(w0), c1 = __popc(w1);
    int p0 = warp_reserve(c0, &g_cnt[2], lane);
    int p1 = warp_reserve(c1, &g_cnt[3], lane);
    int nb = idx << 5;
    while (w0) {
        int b = __ffs(w0) - 1;
        w0 &= w0 - 1;
        g_listN0[p0++] = nb + b;
    }
    while (w1) {
        int b = __ffs(w1) - 1;
        w1 &= w1 - 1;
        g_listN1[p1++] = nb + b;
    }
}

// node projection + el/er (R7-proven form, frozen)
__global__ void k_node(int layer,
                       const float* __restrict__ ent_table,
                       const int*   __restrict__ ent_ids,
                       const float* __restrict__ W_ent,
                       const float* __restrict__ attn_l,
                       const float* __restrict__ attn_r) {
    __shared__ float2 s2[NPB][HID + 2];
    int tid = threadIdx.x;
    int t = tid & 63;
    int g = tid >> 6;
    int cnt = (layer == 0) ? g_cnt[2] : g_cnt[3];
    const int* list = (layer == 0) ? g_listN0 : g_listN1;
    const float* W = W_ent + (size_t)layer * HID * HID;
    float al0 = attn_l[layer * HID + 2 * t], al1 = attn_l[layer * HID + 2 * t + 1];
    float ar0 = attn_r[layer * HID + 2 * t], ar1 = attn_r[layer * HID + 2 * t + 1];

    for (int base = blockIdx.x * NPB; base < cnt; base += gridDim.x * NPB) {
        __syncthreads();
        for (int idx = tid; idx < NPB * 32; idx += 128) {
            int n = idx >> 5, q = idx & 31;
            float4 v = make_float4(0.f, 0.f, 0.f, 0.f);
            int gi = base + n;
            if (gi < cnt) {
                int node = list[gi];
                if (layer == 0) {
                    v = *(const float4*)(ent_table + (size_t)__ldg(&ent_ids[node]) * HID + 4 * q);
                } else {
                    v = *(const float4*)(g_h1 + (size_t)node * HID + 4 * q);
                    float den = g_denomA[node * NH + (q >> 2)];
                    float inv = (den != 0.0f) ? __frcp_rn(den) : 0.0f;
                    v.x *= inv; v.y *= inv; v.z *= inv; v.w *= inv;
                }
            }
            s2[n][4 * q + 0] = make_float2(v.x, v.x);
            s2[n][4 * q + 1] = make_float2(v.y, v.y);
            s2[n][4 * q + 2] = make_float2(v.z, v.z);
            s2[n][4 * q + 3] = make_float2(v.w, v.w);
        }
        __syncthreads();

        unsigned long long acc0 = 0, acc1 = 0, acc2 = 0, acc3 = 0;
        int n0 = g * 4;
#pragma unroll 4
        for (int k = 0; k < HID; k += 4) {
            unsigned long long w0 = *(const unsigned long long*)(W + (size_t)(k + 0) * HID + 2 * t);
            unsigned long long w1 = *(const unsigned long long*)(W + (size_t)(k + 1) * HID + 2 * t);
            unsigned long long w2 = *(const unsigned long long*)(W + (size_t)(k + 2) * HID + 2 * t);
            unsigned long long w3 = *(const unsigned long long*)(W + (size_t)(k + 3) * HID + 2 * t);
            ffma2(acc0, *(const unsigned long long*)&s2[n0 + 0][k + 0], w0);
            ffma2(acc1, *(const unsigned long long*)&s2[n0 + 1][k + 0], w0);
            ffma2(acc2, *(const unsigned long long*)&s2[n0 + 2][k + 0], w0);
            ffma2(acc3, *(const unsigned long long*)&s2[n0 + 3][k + 0], w0);
            ffma2(acc0, *(const unsigned long long*)&s2[n0 + 0][k + 1], w1);
            ffma2(acc1, *(const unsigned long long*)&s2[n0 + 1][k + 1], w1);
            ffma2(acc2, *(const unsigned long long*)&s2[n0 + 2][k + 1], w1);
            ffma2(acc3, *(const unsigned long long*)&s2[n0 + 3][k + 1], w1);
            ffma2(acc0, *(const unsigned long long*)&s2[n0 + 0][k + 2], w2);
            ffma2(acc1, *(const unsigned long long*)&s2[n0 + 1][k + 2], w2);
            ffma2(acc2, *(const unsigned long long*)&s2[n0 + 2][k + 2], w2);
            ffma2(acc3, *(const unsigned long long*)&s2[n0 + 3][k + 2], w2);
            ffma2(acc0, *(const unsigned long long*)&s2[n0 + 0][k + 3], w3);
            ffma2(acc1, *(const unsigned long long*)&s2[n0 + 1][k + 3], w3);
            ffma2(acc2, *(const unsigned long long*)&s2[n0 + 2][k + 3], w3);
            ffma2(acc3, *(const unsigned long long*)&s2[n0 + 3][k + 3], w3);
        }

        unsigned long long accs[4] = {acc0, acc1, acc2, acc3};
#pragma unroll
        for (int n = 0; n < 4; n++) {
            float f0, f1;
            unpack2(accs[n], f0, f1);
            float pl = f0 * al0 + f1 * al1;
            float pr = f0 * ar0 + f1 * ar1;
            pl += __shfl_xor_sync(0xffffffffu, pl, 4);
            pl += __shfl_xor_sync(0xffffffffu, pl, 2);
            pl += __shfl_xor_sync(0xffffffffu, pl, 1);
            pr += __shfl_xor_sync(0xffffffffu, pr, 4);
            pr += __shfl_xor_sync(0xffffffffu, pr, 2);
            pr += __shfl_xor_sync(0xffffffffu, pr, 1);
            int gi = base + n0 + n;
            if (gi < cnt) {
                int node = list[gi];
                *(float2*)(g_feat + (size_t)node * HID + 2 * t) = make_float2(f0, f1);
                if ((t & 7) == 0) {
                    g_el[node * NH + (t >> 3)] = pl;
                    g_er[node * NH + (t >> 3)] = pr;
                }
                if (layer == 0 && bit_test(g_bmN1, node)) {
                    *(float2*)(g_h1 + (size_t)node * HID + 2 * t) = make_float2(0.f, 0.f);
                    if (t < NH) g_denomA[node * NH + t] = 0.0f;
                }
            }
        }
    }
}

// fused edge pass (R7 form)
__global__ void k_edge(int layer, float* __restrict__ dout) {
    int cnt = (layer == 0) ? g_cnt[1] : g_cnt[0];
    const int4* El = (layer == 0) ? g_E1 : g_E2;
    int t = blockIdx.x * blockDim.x + threadIdx.x;
    int j = t & 31;
    int h = j >> 2;
    int e0 = t >> 5;
    int stride = (gridDim.x * blockDim.x) >> 5;
    for (int e = e0; e < cnt; e += stride) {
        int4 p = El[e];
        float v = g_el[p.x * NH + h] + g_er[p.y * NH + h]
                + g_ee[(layer * N_RELS + p.z) * NH + h];
        v = (v > 0.0f) ? v : SLOPE * v;
        float ex = expf(v);
        if ((j & 3) == 0) {
            if (layer == 0) atomicAdd(&g_denomA[p.y * NH + h], ex);
            else            atomicAdd(&g_denomB[p.w * NH + h], ex);
        }
        float4 f  = *(const float4*)(g_feat  + (size_t)p.x * HID + 4 * j);
        float4 rp = *(const float4*)(g_rproj + (size_t)(layer * N_RELS + p.z) * HID + 4 * j);
        float* ob = (layer == 0) ? (g_h1 + (size_t)p.y * HID)
                                 : (dout + (size_t)p.w * HID);
        atomicAdd(ob + 4 * j + 0, (f.x + rp.x) * ex);
        atomicAdd(ob + 4 * j + 1, (f.y + rp.y) * ex);
        atomicAdd(ob + 4 * j + 2, (f.z + rp.z) * ex);
        atomicAdd(ob + 4 * j + 3, (f.w + rp.w) * ex);
    }
}

// final normalize: out[b, col] /= denomB[b, col/16]
__global__ void k_norm(float* __restrict__ dout) {
    int i = blockIdx.x * blockDim.x + threadIdx.x;
    if (i < NB * HID) {
        int b = i >> 7, col = i & 127;
        float den = g_denomB[b * NH + (col >> 4)];
        float inv = (den != 0.0f) ? __frcp_rn(den) : 0.0f;
        dout[i] *= inv;
    }
}

// -------- launch --------
extern "C" void kernel_launch(void* const* d_in, const int* in_sizes, int n_in,
                              void* d_out, int out_size) {
    const float* ent_table = (const float*)d_in[0];
    const float* rel_table = (const float*)d_in[1];
    const float* W_ent     = (const float*)d_in[2];
    const float* W_rel     = (const float*)d_in[3];
    const float* attn_l    = (const float*)d_in[4];
    const float* attn_r    = (const float*)d_in[5];
    const float* attn_e    = (const float*)d_in[6];
    const int*   ent_ids   = (const int*)d_in[7];
    const int*   rel_ids   = (const int*)d_in[8];
    const int*   src       = (const int*)d_in[9];
    const int*   dst       = (const int*)d_in[10];
    const int*   goffs     = (const int*)d_in[11];
    float*       out       = (float*)d_out;

    k_init<<<1, 256>>>(out, goffs);
    k_filter2_rel<<<F2BLKS + 2 * RELBLK, 256>>>((const int4*)src, (const int4*)dst, rel_ids,
                                                rel_table, W_rel, attn_e);
    k_filter1<<<(N_EDGES / 8 + 255) / 256, 256>>>((const int4*)src, (const int4*)dst, rel_ids);
    k_compact<<<(NW + 255) / 256, 256>>>();

    // layer 0 (full frontier N0)
    k_node<<<2048, 128>>>(0, ent_table, ent_ids, W_ent, attn_l, attn_r);
    k_edge<<<512, 256>>>(0, out);

    // layer 1 (frontier N1, output rows only)
    k_node<<<2048, 128>>>(1, ent_table, ent_ids, W_ent, attn_l, attn_r);
    k_edge<<<64, 256>>>(1, out);
    k_norm<<<8, 1024>>>(out);
}

// round 14
// speedup vs baseline: 1.2677x; 1.0535x over previous
#include <cuda_runtime.h>

#define N_NODES 50000
#define N_EDGES 800000
#define N_RELS  500
#define HID     128
#define NH      8
#define NB      64
#define GOFF    781                     // graph_offsets stride (arange(64)*781)
#define SLOPE   0.2f
#define NW      ((N_NODES + 31) / 32)   // bitmask words
#define NPB     8                       // rows per block in tiled GEMV kernels
#define RELBLK  ((N_RELS + NPB - 1) / NPB)   // 63 blocks per layer for k_rel part

// -------- static device scratch --------
__device__ float g_feat[(size_t)N_NODES * HID];
__device__ float g_h1[(size_t)N_NODES * HID];     // layer-1 numerator; h1 = numer/denomA
__device__ float g_el[N_NODES * NH];
__device__ float g_er[N_NODES * NH];
__device__ float g_denomA[N_NODES * NH];
__device__ float g_denomB[NB * NH];
__device__ int4  g_E1[N_EDGES];            // {src, dst, rel, 0}
__device__ int4  g_E2[N_EDGES];            // {src, dst, rel, batch}
__device__ int   g_listN0[N_NODES];
__device__ int   g_listN1[N_NODES];
__device__ unsigned g_bmN1[NW];
__device__ unsigned g_bmN0[NW];
__device__ int   g_cnt[4];                 // 0:|E2| 1:|E1| 2:|N0| 3:|N1|
__device__ float g_rproj[2 * N_RELS * HID];
__device__ float g_ee[2 * N_RELS * NH];

// -------- helpers --------
__device__ __forceinline__ int warp_reserve(int c, int* counter, int lane) {
    int pre = c;
#pragma unroll
    for (int off = 1; off < 32; off <<= 1) {
        int v = __shfl_up_sync(0xffffffffu, pre, off);
        if (lane >= off) pre += v;
    }
    int total = __shfl_sync(0xffffffffu, pre, 31);
    int base = 0;
    if (lane == 31 && total) base = atomicAdd(counter, total);
    base = __shfl_sync(0xffffffffu, base, 31);
    return base + pre - c;
}
__device__ __forceinline__ int bit_test(const unsigned* bm, int n) {
    return (bm[n >> 5] >> (n & 31)) & 1;
}
__device__ __forceinline__ int in_s2(int n) {   // n == 781*k, k < 64
    return ((unsigned)n % GOFF == 0u) && ((unsigned)n < (unsigned)(GOFF * NB));
}
__device__ __forceinline__ void ffma2(unsigned long long& d,
                                      unsigned long long a, unsigned long long b) {
    asm("fma.rn.f32x2 %0, %1, %2, %0;" : "+l"(d) : "l"(a), "l"(b));
}
__device__ __forceinline__ void unpack2(unsigned long long v, float& lo, float& hi) {
    asm("mov.b64 {%0, %1}, %2;" : "=f"(lo), "=f"(hi) : "l"(v));
}

// -------- kernels --------
// blocks [0, 2*RELBLK): tiled relation projection + relation attention scores
// block 2*RELBLK: zero-init + seed masks. 128 threads everywhere.
__global__ void k_setup(float* __restrict__ dout, const int* __restrict__ offs,
                        const float* __restrict__ rel_table,
                        const float* __restrict__ W_rel,
                        const float* __restrict__ attn_e) {
    int tid = threadIdx.x;
    if (blockIdx.x == 2 * RELBLK) {
        for (int i = tid; i < NW; i += 128) { g_bmN1[i] = 0u; g_bmN0[i] = 0u; }
        for (int i = tid; i < NB * HID; i += 128) dout[i] = 0.0f;
        for (int i = tid; i < NB * NH; i += 128) g_denomB[i] = 0.0f;
        if (tid < 4) g_cnt[tid] = 0;
        __syncthreads();
        if (tid < NB) {
            int n = offs[tid];
            atomicOr(&g_bmN1[n >> 5], 1u << (n & 31));
        }
        return;
    }
    __shared__ float2 s2[NPB][HID + 2];
    int l = blockIdx.x / RELBLK;
    int base = (blockIdx.x % RELBLK) * NPB;
    int t = tid & 63;
    int g = tid >> 6;
    const float* W = W_rel + (size_t)l * HID * HID;
    float ae0 = attn_e[l * HID + 2 * t], ae1 = attn_e[l * HID + 2 * t + 1];

    for (int idx = tid; idx < NPB * 32; idx += 128) {
        int n = idx >> 5, q = idx & 31;
        float4 v = make_float4(0.f, 0.f, 0.f, 0.f);
        if (base + n < N_RELS)
            v = *(const float4*)(rel_table + (size_t)(base + n) * HID + 4 * q);
        s2[n][4 * q + 0] = make_float2(v.x, v.x);
        s2[n][4 * q + 1] = make_float2(v.y, v.y);
        s2[n][4 * q + 2] = make_float2(v.z, v.z);
        s2[n][4 * q + 3] = make_float2(v.w, v.w);
    }
    __syncthreads();

    unsigned long long acc0 = 0, acc1 = 0, acc2 = 0, acc3 = 0;
    int n0 = g * 4;
#pragma unroll 4
    for (int k = 0; k < HID; k += 4) {
        unsigned long long w0 = *(const unsigned long long*)(W + (size_t)(k + 0) * HID + 2 * t);
        unsigned long long w1 = *(const unsigned long long*)(W + (size_t)(k + 1) * HID + 2 * t);
        unsigned long long w2 = *(const unsigned long long*)(W + (size_t)(k + 2) * HID + 2 * t);
        unsigned long long w3 = *(const unsigned long long*)(W + (size_t)(k + 3) * HID + 2 * t);
        ffma2(acc0, *(const unsigned long long*)&s2[n0 + 0][k + 0], w0);
        ffma2(acc1, *(const unsigned long long*)&s2[n0 + 1][k + 0], w0);
        ffma2(acc2, *(const unsigned long long*)&s2[n0 + 2][k + 0], w0);
        ffma2(acc3, *(const unsigned long long*)&s2[n0 + 3][k + 0], w0);
        ffma2(acc0, *(const unsigned long long*)&s2[n0 + 0][k + 1], w1);
        ffma2(acc1, *(const unsigned long long*)&s2[n0 + 1][k + 1], w1);
        ffma2(acc2, *(const unsigned long long*)&s2[n0 + 2][k + 1], w1);
        ffma2(acc3, *(const unsigned long long*)&s2[n0 + 3][k + 1], w1);
        ffma2(acc0, *(const unsigned long long*)&s2[n0 + 0][k + 2], w2);
        ffma2(acc1, *(const unsigned long long*)&s2[n0 + 1][k + 2], w2);
        ffma2(acc2, *(const unsigned long long*)&s2[n0 + 2][k + 2], w2);
        ffma2(acc3, *(const unsigned long long*)&s2[n0 + 3][k + 2], w2);
        ffma2(acc0, *(const unsigned long long*)&s2[n0 + 0][k + 3], w3);
        ffma2(acc1, *(const unsigned long long*)&s2[n0 + 1][k + 3], w3);
        ffma2(acc2, *(const unsigned long long*)&s2[n0 + 2][k + 3], w3);
        ffma2(acc3, *(const unsigned long long*)&s2[n0 + 3][k + 3], w3);
    }

    unsigned long long accs[4] = {acc0, acc1, acc2, acc3};
#pragma unroll
    for (int n = 0; n < 4; n++) {
        float f0, f1;
        unpack2(accs[n], f0, f1);
        float pe = f0 * ae0 + f1 * ae1;
        pe += __shfl_xor_sync(0xffffffffu, pe, 4);
        pe += __shfl_xor_sync(0xffffffffu, pe, 2);
        pe += __shfl_xor_sync(0xffffffffu, pe, 1);
        int r = base + n0 + n;
        if (r < N_RELS) {
            int b = l * N_RELS + r;
            *(float2*)(g_rproj + (size_t)b * HID + 2 * t) = make_float2(f0, f1);
            if ((t & 7) == 0) g_ee[b * NH + (t >> 3)] = pe;
        }
    }
}

// layer-2 edge filter: dst in S2 via ARITHMETIC test (no mask loads).
// Two int4 chunks (8 edges) per thread, R7 layout.
__global__ void k_filter2(const int4* __restrict__ src4, const int4* __restrict__ dst4,
                          const int* __restrict__ rel_ids) {
    const int half = N_EDGES / 8;
    int base = blockIdx.x * blockDim.x + threadIdx.x;
    int lane = threadIdx.x & 31;
    unsigned m0 = 0, m1 = 0;
    int4 d0, d1;
    if (base < half) {
        d0 = __ldg(&dst4[base]);
        d1 = __ldg(&dst4[base + half]);
        m0 = (in_s2(d0.x) ? 1u : 0u) | (in_s2(d0.y) ? 2u : 0u)
           | (in_s2(d0.z) ? 4u : 0u) | (in_s2(d0.w) ? 8u : 0u);
        m1 = (in_s2(d1.x) ? 1u : 0u) | (in_s2(d1.y) ? 2u : 0u)
           | (in_s2(d1.z) ? 4u : 0u) | (in_s2(d1.w) ? 8u : 0u);
    }
    int c = __popc(m0) + __popc(m1);
    int pos = warp_reserve(c, &g_cnt[0], lane);
    if (m0) {
        int i0 = base;
        int4 s = __ldg(&src4[i0]);
        if (m0 & 1u) { g_E2[pos++] = make_int4(s.x, d0.x, __ldg(&rel_ids[4*i0+0]), (int)((unsigned)d0.x / GOFF)); atomicOr(&g_bmN1[s.x >> 5], 1u << (s.x & 31)); }
        if (m0 & 2u) { g_E2[pos++] = make_int4(s.y, d0.y, __ldg(&rel_ids[4*i0+1]), (int)((unsigned)d0.y / GOFF)); atomicOr(&g_bmN1[s.y >> 5], 1u << (s.y & 31)); }
        if (m0 & 4u) { g_E2[pos++] = make_int4(s.z, d0.z, __ldg(&rel_ids[4*i0+2]), (int)((unsigned)d0.z / GOFF)); atomicOr(&g_bmN1[s.z >> 5], 1u << (s.z & 31)); }
        if (m0 & 8u) { g_E2[pos++] = make_int4(s.w, d0.w, __ldg(&rel_ids[4*i0+3]), (int)((unsigned)d0.w / GOFF)); atomicOr(&g_bmN1[s.w >> 5], 1u << (s.w & 31)); }
    }
    if (m1) {
        int i1 = base + half;
        int4 s = __ldg(&src4[i1]);
        if (m1 & 1u) { g_E2[pos++] = make_int4(s.x, d1.x, __ldg(&rel_ids[4*i1+0]), (int)((unsigned)d1.x / GOFF)); atomicOr(&g_bmN1[s.x >> 5], 1u << (s.x & 31)); }
        if (m1 & 2u) { g_E2[pos++] = make_int4(s.y, d1.y, __ldg(&rel_ids[4*i1+1]), (int)((unsigned)d1.y / GOFF)); atomicOr(&g_bmN1[s.y >> 5], 1u << (s.y & 31)); }
        if (m1 & 4u) { g_E2[pos++] = make_int4(s.z, d1.z, __ldg(&rel_ids[4*i1+2]), (int)((unsigned)d1.z / GOFF)); atomicOr(&g_bmN1[s.z >> 5], 1u << (s.z & 31)); }
        if (m1 & 8u) { g_E2[pos++] = make_int4(s.w, d1.w, __ldg(&rel_ids[4*i1+3]), (int)((unsigned)d1.w / GOFF)); atomicOr(&g_bmN1[s.w >> 5], 1u << (s.w & 31)); }
    }
}

// layer-1 edge filter: dst in N1 (R7 form)
__global__ void k_filter1(const int4* __restrict__ src4, const int4* __restrict__ dst4,
                          const int* __restrict__ rel_ids) {
    const int half = N_EDGES / 8;
    int base = blockIdx.x * blockDim.x + threadIdx.x;
    int lane = threadIdx.x & 31;
    unsigned m0 = 0, m1 = 0;
    int4 d0, d1;
    if (base < half) {
        d0 = __ldg(&dst4[base]);
        d1 = __ldg(&dst4[base + half]);
        unsigned w0 = g_bmN1[d0.x >> 5], w1 = g_bmN1[d0.y >> 5];
        unsigned w2 = g_bmN1[d0.z >> 5], w3 = g_bmN1[d0.w >> 5];
        unsigned w4 = g_bmN1[d1.x >> 5], w5 = g_bmN1[d1.y >> 5];
        unsigned w6 = g_bmN1[d1.z >> 5], w7 = g_bmN1[d1.w >> 5];
        m0 = ((w0 >> (d0.x & 31)) & 1u) | (((w1 >> (d0.y & 31)) & 1u) << 1)
           | (((w2 >> (d0.z & 31)) & 1u) << 2) | (((w3 >> (d0.w & 31)) & 1u) << 3);
        m1 = ((w4 >> (d1.x & 31)) & 1u) | (((w5 >> (d1.y & 31)) & 1u) << 1)
           | (((w6 >> (d1.z & 31)) & 1u) << 2) | (((w7 >> (d1.w & 31)) & 1u) << 3);
    }
    int c = __popc(m0) + __popc(m1);
    int pos = warp_reserve(c, &g_cnt[1], lane);
    if (m0) {
        int i0 = base;
        int4 s = __ldg(&src4[i0]);
        if (m0 & 1u) { g_E1[pos++] = make_int4(s.x, d0.x, __ldg(&rel_ids[4*i0+0]), 0); atomicOr(&g_bmN0[s.x >> 5], 1u << (s.x & 31)); }
        if (m0 & 2u) { g_E1[pos++] = make_int4(s.y, d0.y, __ldg(&rel_ids[4*i0+1]), 0); atomicOr(&g_bmN0[s.y >> 5], 1u << (s.y & 31)); }
        if (m0 & 4u) { g_E1[pos++] = make_int4(s.z, d0.z, __ldg(&rel_ids[4*i0+2]), 0); atomicOr(&g_bmN0[s.z >> 5], 1u << (s.z & 31)); }
        if (m0 & 8u) { g_E1[pos++] = make_int4(s.w, d0.w, __ldg(&rel_ids[4*i0+3]), 0); atomicOr(&g_bmN0[s.w >> 5], 1u << (s.w & 31)); }
    }
    if (m1) {
        int i1 = base + half;
        int4 s = __ldg(&src4[i1]);
        if (m1 & 1u) { g_E1[pos++] = make_int4(s.x, d1.x, __ldg(&rel_ids[4*i1+0]), 0); atomicOr(&g_bmN0[s.x >> 5], 1u << (s.x & 31)); }
        if (m1 & 2u) { g_E1[pos++] = make_int4(s.y, d1.y, __ldg(&rel_ids[4*i1+1]), 0); atomicOr(&g_bmN0[s.y >> 5], 1u << (s.y & 31)); }
        if (m1 & 4u) { g_E1[pos++] = make_int4(s.z, d1.z, __ldg(&rel_ids[4*i1+2]), 0); atomicOr(&g_bmN0[s.z >> 5], 1u << (s.z & 31)); }
        if (m1 & 8u) { g_E1[pos++] = make_int4(s.w, d1.w, __ldg(&rel_ids[4*i1+3]), 0); atomicOr(&g_bmN0[s.w >> 5], 1u << (s.w & 31)); }
    }
}

// word-parallel compaction: lists only (R7 form)
__global__ void k_compact() {
    int idx = blockIdx.x * blockDim.x + threadIdx.x;
    int lane = threadIdx.x & 31;
    unsigned w1 = 0, w0 = 0;
    if (idx < NW) {
        w1 = g_bmN1[idx];
        w0 = g_bmN0[idx] | w1;
    }
    int c0 = __popc(w0), c1 = __popc(w1);
    int p0 = warp_reserve(c0, &g_cnt[2], lane);
    int p1 = warp_reserve(c1, &g_cnt[3], lane);
    int nb = idx << 5;
    while (w0) {
        int b = __ffs(w0) - 1;
        w0 &= w0 - 1;
        g_listN0[p0++] = nb + b;
    }
    while (w1) {
        int b = __ffs(w1) - 1;
        w1 &= w1 - 1;
        g_listN1[p1++] = nb + b;
    }
}

// node projection + el/er (R7-proven form, frozen)
__global__ void k_node(int layer,
                       const float* __restrict__ ent_table,
                       const int*   __restrict__ ent_ids,
                       const float* __restrict__ W_ent,
                       const float* __restrict__ attn_l,
                       const float* __restrict__ attn_r) {
    __shared__ float2 s2[NPB][HID + 2];
    int tid = threadIdx.x;
    int t = tid & 63;
    int g = tid >> 6;
    int cnt = (layer == 0) ? g_cnt[2] : g_cnt[3];
    const int* list = (layer == 0) ? g_listN0 : g_listN1;
    const float* W = W_ent + (size_t)layer * HID * HID;
    float al0 = attn_l[layer * HID + 2 * t], al1 = attn_l[layer * HID + 2 * t + 1];
    float ar0 = attn_r[layer * HID + 2 * t], ar1 = attn_r[layer * HID + 2 * t + 1];

    for (int base = blockIdx.x * NPB; base < cnt; base += gridDim.x * NPB) {
        __syncthreads();
        for (int idx = tid; idx < NPB * 32; idx += 128) {
            int n = idx >> 5, q = idx & 31;
            float4 v = make_float4(0.f, 0.f, 0.f, 0.f);
            int gi = base + n;
            if (gi < cnt) {
                int node = list[gi];
                if (layer == 0) {
                    v = *(const float4*)(ent_table + (size_t)__ldg(&ent_ids[node]) * HID + 4 * q);
                } else {
                    v = *(const float4*)(g_h1 + (size_t)node * HID + 4 * q);
                    float den = g_denomA[node * NH + (q >> 2)];
                    float inv = (den != 0.0f) ? __frcp_rn(den) : 0.0f;
                    v.x *= inv; v.y *= inv; v.z *= inv; v.w *= inv;
                }
            }
            s2[n][4 * q + 0] = make_float2(v.x, v.x);
            s2[n][4 * q + 1] = make_float2(v.y, v.y);
            s2[n][4 * q + 2] = make_float2(v.z, v.z);
            s2[n][4 * q + 3] = make_float2(v.w, v.w);
        }
        __syncthreads();

        unsigned long long acc0 = 0, acc1 = 0, acc2 = 0, acc3 = 0;
        int n0 = g * 4;
#pragma unroll 4
        for (int k = 0; k < HID; k += 4) {
            unsigned long long w0 = *(const unsigned long long*)(W + (size_t)(k + 0) * HID + 2 * t);
            unsigned long long w1 = *(const unsigned long long*)(W + (size_t)(k + 1) * HID + 2 * t);
            unsigned long long w2 = *(const unsigned long long*)(W + (size_t)(k + 2) * HID + 2 * t);
            unsigned long long w3 = *(const unsigned long long*)(W + (size_t)(k + 3) * HID + 2 * t);
            ffma2(acc0, *(const unsigned long long*)&s2[n0 + 0][k + 0], w0);
            ffma2(acc1, *(const unsigned long long*)&s2[n0 + 1][k + 0], w0);
            ffma2(acc2, *(const unsigned long long*)&s2[n0 + 2][k + 0], w0);
            ffma2(acc3, *(const unsigned long long*)&s2[n0 + 3][k + 0], w0);
            ffma2(acc0, *(const unsigned long long*)&s2[n0 + 0][k + 1], w1);
            ffma2(acc1, *(const unsigned long long*)&s2[n0 + 1][k + 1], w1);
            ffma2(acc2, *(const unsigned long long*)&s2[n0 + 2][k + 1], w1);
            ffma2(acc3, *(const unsigned long long*)&s2[n0 + 3][k + 1], w1);
            ffma2(acc0, *(const unsigned long long*)&s2[n0 + 0][k + 2], w2);
            ffma2(acc1, *(const unsigned long long*)&s2[n0 + 1][k + 2], w2);
            ffma2(acc2, *(const unsigned long long*)&s2[n0 + 2][k + 2], w2);
            ffma2(acc3, *(const unsigned long long*)&s2[n0 + 3][k + 2], w2);
            ffma2(acc0, *(const unsigned long long*)&s2[n0 + 0][k + 3], w3);
            ffma2(acc1, *(const unsigned long long*)&s2[n0 + 1][k + 3], w3);
            ffma2(acc2, *(const unsigned long long*)&s2[n0 + 2][k + 3], w3);
            ffma2(acc3, *(const unsigned long long*)&s2[n0 + 3][k + 3], w3);
        }

        unsigned long long accs[4] = {acc0, acc1, acc2, acc3};
#pragma unroll
        for (int n = 0; n < 4; n++) {
            float f0, f1;
            unpack2(accs[n], f0, f1);
            float pl = f0 * al0 + f1 * al1;
            float pr = f0 * ar0 + f1 * ar1;
            pl += __shfl_xor_sync(0xffffffffu, pl, 4);
            pl += __shfl_xor_sync(0xffffffffu, pl, 2);
            pl += __shfl_xor_sync(0xffffffffu, pl, 1);
            pr += __shfl_xor_sync(0xffffffffu, pr, 4);
            pr += __shfl_xor_sync(0xffffffffu, pr, 2);
            pr += __shfl_xor_sync(0xffffffffu, pr, 1);
            int gi = base + n0 + n;
            if (gi < cnt) {
                int node = list[gi];
                *(float2*)(g_feat + (size_t)node * HID + 2 * t) = make_float2(f0, f1);
                if ((t & 7) == 0) {
                    g_el[node * NH + (t >> 3)] = pl;
                    g_er[node * NH + (t >> 3)] = pr;
                }
                if (layer == 0 && bit_test(g_bmN1, node)) {
                    *(float2*)(g_h1 + (size_t)node * HID + 2 * t) = make_float2(0.f, 0.f);
                    if (t < NH) g_denomA[node * NH + t] = 0.0f;
                }
            }
        }
    }
}

// fused edge pass (R7 form)
__global__ void k_edge(int layer, float* __restrict__ dout) {
    int cnt = (layer == 0) ? g_cnt[1] : g_cnt[0];
    const int4* El = (layer == 0) ? g_E1 : g_E2;
    int t = blockIdx.x * blockDim.x + threadIdx.x;
    int j = t & 31;
    int h = j >> 2;
    int e0 = t >> 5;
    int stride = (gridDim.x * blockDim.x) >> 5;
    for (int e = e0; e < cnt; e += stride) {
        int4 p = El[e];
        float v = g_el[p.x * NH + h] + g_er[p.y * NH + h]
                + g_ee[(layer * N_RELS + p.z) * NH + h];
        v = (v > 0.0f) ? v : SLOPE * v;
        float ex = expf(v);
        if ((j & 3) == 0) {
            if (layer == 0) atomicAdd(&g_denomA[p.y * NH + h], ex);
            else            atomicAdd(&g_denomB[p.w * NH + h], ex);
        }
        float4 f  = *(const float4*)(g_feat  + (size_t)p.x * HID + 4 * j);
        float4 rp = *(const float4*)(g_rproj + (size_t)(layer * N_RELS + p.z) * HID + 4 * j);
        float* ob = (layer == 0) ? (g_h1 + (size_t)p.y * HID)
                                 : (dout + (size_t)p.w * HID);
        atomicAdd(ob + 4 * j + 0, (f.x + rp.x) * ex);
        atomicAdd(ob + 4 * j + 1, (f.y + rp.y) * ex);
        atomicAdd(ob + 4 * j + 2, (f.z + rp.z) * ex);
        atomicAdd(ob + 4 * j + 3, (f.w + rp.w) * ex);
    }
}

// final normalize: out[b, col] /= denomB[b, col/16]
__global__ void k_norm(float* __restrict__ dout) {
    int i = blockIdx.x * blockDim.x + threadIdx.x;
    if (i < NB * HID) {
        int b = i >> 7, col = i & 127;
        float den = g_denomB[b * NH + (col >> 4)];
        float inv = (den != 0.0f) ? __frcp_rn(den) : 0.0f;
        dout[i] *= inv;
    }
}

// -------- launch --------
extern "C" void kernel_launch(void* const* d_in, const int* in_sizes, int n_in,
                              void* d_out, int out_size) {
    const float* ent_table = (const float*)d_in[0];
    const float* rel_table = (const float*)d_in[1];
    const float* W_ent     = (const float*)d_in[2];
    const float* W_rel     = (const float*)d_in[3];
    const float* attn_l    = (const float*)d_in[4];
    const float* attn_r    = (const float*)d_in[5];
    const float* attn_e    = (const float*)d_in[6];
    const int*   ent_ids   = (const int*)d_in[7];
    const int*   rel_ids   = (const int*)d_in[8];
    const int*   src       = (const int*)d_in[9];
    const int*   dst       = (const int*)d_in[10];
    const int*   goffs     = (const int*)d_in[11];
    float*       out       = (float*)d_out;

    k_setup<<<2 * RELBLK + 1, 128>>>(out, goffs, rel_table, W_rel, attn_e);
    k_filter2<<<(N_EDGES / 8 + 255) / 256, 256>>>((const int4*)src, (const int4*)dst, rel_ids);
    k_filter1<<<(N_EDGES / 8 + 255) / 256, 256>>>((const int4*)src, (const int4*)dst, rel_ids);
    k_compact<<<(NW + 255) / 256, 256>>>();

    // layer 0 (full frontier N0)
    k_node<<<2048, 128>>>(0, ent_table, ent_ids, W_ent, attn_l, attn_r);
    k_edge<<<512, 256>>>(0, out);

    // layer 1 (frontier N1, output rows only)
    k_node<<<2048, 128>>>(1, ent_table, ent_ids, W_ent, attn_l, attn_r);
    k_edge<<<64, 256>>>(1, out);
    k_norm<<<8, 1024>>>(out);
}